// round 16
// baseline (speedup 1.0000x reference)
#include <cuda_runtime.h>

#define BSZ 8192
#define TSTEPS 128
#define NN 25
// HID = 4, gates = 16

// Scratch (allocation-free rule: static __device__ arrays)
__device__ float g_H[BSZ * 200];                // final hidden concat, (bs, 200)

typedef unsigned long long u64;

// ---------------------------------------------------------------------------
// f32x2 packed helpers
// ---------------------------------------------------------------------------
__device__ __forceinline__ u64 packf2(float lo, float hi) {
    u64 r; asm("mov.b64 %0, {%1, %2};" : "=l"(r) : "f"(lo), "f"(hi)); return r;
}
__device__ __forceinline__ u64 bcast2(float v) { return packf2(v, v); }
__device__ __forceinline__ void unpackf2(u64 v, float& lo, float& hi) {
    asm("mov.b64 {%0, %1}, %2;" : "=f"(lo), "=f"(hi) : "l"(v));
}
__device__ __forceinline__ u64 fma2(u64 a, u64 b, u64 c) {
    u64 r; asm("fma.rn.f32x2 %0, %1, %2, %3;" : "=l"(r) : "l"(a), "l"(b), "l"(c));
    return r;
}
// 64-bit shuffles within the 4-lane group (2x SHFL.32)
__device__ __forceinline__ u64 shflx64(u64 v, int m) {
    unsigned lo = (unsigned)v, hi = (unsigned)(v >> 32);
    lo = __shfl_xor_sync(0xffffffffu, lo, m, 4);
    hi = __shfl_xor_sync(0xffffffffu, hi, m, 4);
    return ((u64)hi << 32) | lo;
}
__device__ __forceinline__ u64 shflb64(u64 v) {   // broadcast from lane 3 of group
    unsigned lo = (unsigned)v, hi = (unsigned)(v >> 32);
    lo = __shfl_sync(0xffffffffu, lo, 3, 4);
    hi = __shfl_sync(0xffffffffu, hi, 3, 4);
    return ((u64)hi << 32) | lo;
}

// ---------------------------------------------------------------------------
// cp.async helpers (4-byte LDGSTS)
// ---------------------------------------------------------------------------
__device__ __forceinline__ unsigned smem_u32(const void* p) {
    unsigned a;
    asm("{ .reg .u64 t; cvta.to.shared.u64 t, %1; cvt.u32.u64 %0, t; }"
        : "=r"(a) : "l"(p));
    return a;
}
__device__ __forceinline__ void cp_async4(unsigned dst, const void* src) {
    asm volatile("cp.async.ca.shared.global [%0], [%1], 4;" :: "r"(dst), "l"(src));
}
__device__ __forceinline__ void cp_commit() {
    asm volatile("cp.async.commit_group;");
}
template <int N>
__device__ __forceinline__ void cp_wait() {
    asm volatile("cp.async.wait_group %0;" :: "n"(N));
}

// ---------------------------------------------------------------------------
// MUFU.TANH-based activations (1 MUFU each) + precise sigmoid (FF head)
// ---------------------------------------------------------------------------
__device__ __forceinline__ float tanh_mufu(float x) {
    float y; asm("tanh.approx.f32 %0, %1;" : "=f"(y) : "f"(x)); return y;
}
__device__ __forceinline__ float sigf(float x) {   // precise (FF head)
    return __fdividef(1.0f, 1.0f + __expf(-x));
}

// ---------------------------------------------------------------------------
// Kernel: grid-LSTM recurrence (R15 structure) with
//   (a) DIRECT x loads: two 4-byte cp.async per node straight from the
//       original (bs, N, T) layout — the transpose kernel is gone. L2 sector
//       reuse (8 consecutive t per 32B sector, ~6.6MB working set) keeps DRAM
//       traffic at ~105MB; the double buffer hides all latency.
//   (b) 32-thread blocks: 1024 blocks spread 7/6 per SM instead of 512
//       2-warp blocks spreading 4/3 — max warps/SMSP drops 2.0 -> 1.75.
// ---------------------------------------------------------------------------
template <int STEPS>
__global__ __launch_bounds__(32) void rec_kernel(
    const float* __restrict__ x,
    const float* __restrict__ h0f, const float* __restrict__ c0f,
    const float* __restrict__ h0b, const float* __restrict__ c0b,
    const float* __restrict__ Wxf, const float* __restrict__ Whf,
    const float* __restrict__ Wnf, const float* __restrict__ bf,
    const float* __restrict__ Wxb, const float* __restrict__ Whb,
    const float* __restrict__ Wnb, const float* __restrict__ bbk) {
    __shared__ u64 sm_x[2][NN][32];            // double-buffered x stage

    int tx   = threadIdx.x;
    int tid  = blockIdx.x * 32 + tx;           // 0 .. 32767
    int u    = tid & 3;
    int gid  = tid >> 2;                       // 0 .. 8191
    int pair = gid & 4095;
    int dir  = gid >> 12;                      // 0 = fwd, 1 = bwd
    int b0   = pair * 2;

    const float* Wx = dir ? Wxb : Wxf;
    const float* Wh = dir ? Whb : Whf;
    const float* Wn = dir ? Wnb : Wnf;
    const float* bv = dir ? bbk : bf;
    const float* h0 = dir ? h0b : h0f;
    const float* c0 = dir ? c0b : c0f;

    // x rows for this thread's batch pair: x[(b*NN + i)*TSTEPS + t]
    const float* xa = x + (size_t)b0 * NN * TSTEPS;        // batch b0
    const float* xb = xa + NN * TSTEPS;                    // batch b0+1

    // Per-gate scale: 0.5 for sigmoid gates (g=0,1,2), 1.0 for cc (g=3)
    u64 wx2[4], b2[4], wh2[4][4], wu2[4], wd2[4], wl2[4], wr2[4];
    int rl = dir ? 3 : 2;   // Wn row providing LEFT weight
    int rr = dir ? 2 : 3;
#pragma unroll
    for (int g = 0; g < 4; g++) {
        float s   = (g == 3) ? 1.0f : 0.5f;
        int   col = g * 4 + u;
        wx2[g] = bcast2(s * Wx[col]);
        b2[g]  = bcast2(s * bv[col]);
#pragma unroll
        for (int j = 0; j < 4; j++)
            wh2[j][g] = bcast2(s * Wh[(u ^ j) * 16 + col]);  // j-th butterfly arrival
        wu2[g] = bcast2(s * Wn[0 * 16 + col]);
        wd2[g] = bcast2(s * Wn[1 * 16 + col]);
        wl2[g] = bcast2(s * Wn[rl * 16 + col]);
        wr2[g] = bcast2(s * Wn[rr * 16 + col]);
    }

    u64 h[NN];
    float ca[NN], cb[NN];
#pragma unroll
    for (int i = 0; i < NN; i++) {
        int base = (i * BSZ + b0) * 4 + u;
        h[i]  = packf2(h0[base], h0[base + 4]);
        ca[i] = c0[base];
        cb[i] = c0[base + 4];
    }

    // Stage timestep 0
    {
        int tt0 = dir ? (TSTEPS - 1) : 0;
#pragma unroll
        for (int i = 0; i < NN; i++) {
            unsigned d = smem_u32(&sm_x[0][i][tx]);
            cp_async4(d,     xa + i * TSTEPS + tt0);
            cp_async4(d + 4, xb + i * TSTEPS + tt0);
        }
        cp_commit();
    }

#pragma unroll 1
    for (int t = 0; t < STEPS; t++) {
        int cur = t & 1;
        // stage t+1 while computing t
        if (t + 1 < STEPS) {
            int ttn = dir ? (TSTEPS - 2 - t) : (t + 1);
#pragma unroll
            for (int i = 0; i < NN; i++) {
                unsigned d = smem_u32(&sm_x[cur ^ 1][i][tx]);
                cp_async4(d,     xa + i * TSTEPS + ttn);
                cp_async4(d + 4, xb + i * TSTEPS + ttn);
            }
            cp_commit();
            cp_wait<1>();   // current-step group complete; next may be in flight
        } else {
            cp_wait<0>();
        }

#pragma unroll
        for (int i = 0; i < NN; i++) {
            u64 vx = sm_x[cur][i][tx];
            u64 v0 = h[i];
            // Issue ALL broadcasts up front; the chain-critical LEFT value's
            // SHFL latency is covered by the gate FMAs below.
            u64 nL = 0, nU = 0, nD = 0, nR = 0;
            if (i >= 1) nL = shflb64(h[i - 1]);   // fresh (this step)
            if (i >= 5) nU = shflb64(h[i - 5]);   // fresh
            if (i < 20) nD = shflb64(h[i + 5]);   // stale (prev step)
            if (i < 24) nR = shflb64(h[i + 1]);   // stale
            u64 v1 = shflx64(v0, 1);
            u64 v2 = shflx64(v0, 2);
            u64 v3 = shflx64(v1, 2);

            u64 G[4];
#pragma unroll
            for (int g = 0; g < 4; g++) {
                G[g] = fma2(vx, wx2[g], b2[g]);
                G[g] = fma2(v0, wh2[0][g], G[g]);
                G[g] = fma2(v1, wh2[1][g], G[g]);
                G[g] = fma2(v2, wh2[2][g], G[g]);
                G[g] = fma2(v3, wh2[3][g], G[g]);
            }
            if (i < 20) {
#pragma unroll
                for (int g = 0; g < 4; g++) G[g] = fma2(nD, wd2[g], G[g]);
            }
            if (i < 24) {
#pragma unroll
                for (int g = 0; g < 4; g++) G[g] = fma2(nR, wr2[g], G[g]);
            }
            if (i >= 5) {
#pragma unroll
                for (int g = 0; g < 4; g++) G[g] = fma2(nU, wu2[g], G[g]);
            }
            if (i >= 1) {   // LEFT term last: shortest exposure on the chain
#pragma unroll
                for (int g = 0; g < 4; g++) G[g] = fma2(nL, wl2[g], G[g]);
            }

            float i_a, i_b, f_a, f_b, o_a, o_b, c_a, c_b;
            unpackf2(G[0], i_a, i_b);
            unpackf2(G[1], f_a, f_b);
            unpackf2(G[2], o_a, o_b);
            unpackf2(G[3], c_a, c_b);

            // batch 0 (gates pre-scaled by 0.5 for sigmoids)
            float sia = fmaf(0.5f, tanh_mufu(i_a), 0.5f);
            float sfa = fmaf(0.5f, tanh_mufu(f_a), 0.5f);
            float soa = fmaf(0.5f, tanh_mufu(o_a), 0.5f);
            float tca = tanh_mufu(c_a);
            float nca = fmaf(sfa, ca[i], sia * tca);
            ca[i] = nca;
            float nha = soa * tanh_mufu(nca);
            // batch 1
            float sib = fmaf(0.5f, tanh_mufu(i_b), 0.5f);
            float sfb = fmaf(0.5f, tanh_mufu(f_b), 0.5f);
            float sob = fmaf(0.5f, tanh_mufu(o_b), 0.5f);
            float tcb = tanh_mufu(c_b);
            float ncb = fmaf(sfb, cb[i], sib * tcb);
            cb[i] = ncb;
            float nhb = sob * tanh_mufu(ncb);

            h[i] = packf2(nha, nhb);
        }
    }

    // H[b, i*8 + dir*4 + u] = h[i]
#pragma unroll
    for (int i = 0; i < NN; i++) {
        float ha, hb;
        unpackf2(h[i], ha, hb);
        g_H[b0 * 200 + i * 8 + dir * 4 + u]       = ha;
        g_H[(b0 + 1) * 200 + i * 8 + dir * 4 + u] = hb;
    }
}

// ---------------------------------------------------------------------------
// Kernel: FF head. 16 batch rows per block, 128 threads (one per neuron).
// ff = sigmoid(H @ W_ff + b_ff); out = softmax(ff @ W_out + b_out)
// ---------------------------------------------------------------------------
__global__ void ff_kernel(const float* __restrict__ Wff, const float* __restrict__ bff,
                          const float* __restrict__ Wout, const float* __restrict__ bout,
                          float* __restrict__ out) {
    __shared__ float Hs[16 * 200];
    __shared__ float Fs[16 * 128];
    int k  = threadIdx.x;        // neuron 0..127
    int b0 = blockIdx.x * 16;

    for (int idx = k; idx < 16 * 200; idx += 128)
        Hs[idx] = g_H[b0 * 200 + idx];
    __syncthreads();

    float acc[16];
    float bk = bff[k];
#pragma unroll
    for (int m = 0; m < 16; m++) acc[m] = bk;
#pragma unroll 4
    for (int j = 0; j < 200; j++) {
        float w = Wff[j * 128 + k];
#pragma unroll
        for (int m = 0; m < 16; m++) acc[m] = fmaf(Hs[m * 200 + j], w, acc[m]);
    }
#pragma unroll
    for (int m = 0; m < 16; m++) Fs[m * 128 + k] = sigf(acc[m]);
    __syncthreads();

    if (k < 16) {
        float s0 = bout[0], s1 = bout[1];
#pragma unroll 4
        for (int j = 0; j < 128; j++) {
            float f = Fs[k * 128 + j];
            s0 = fmaf(f, Wout[j * 2 + 0], s0);
            s1 = fmaf(f, Wout[j * 2 + 1], s1);
        }
        // softmax over 2 logits == sigmoid of difference
        out[(b0 + k) * 2 + 0] = sigf(s0 - s1);
        out[(b0 + k) * 2 + 1] = sigf(s1 - s0);
    }
}

// ---------------------------------------------------------------------------
extern "C" void kernel_launch(void* const* d_in, const int* in_sizes, int n_in,
                              void* d_out, int out_size) {
    const float* x    = (const float*)d_in[0];
    const float* h0f  = (const float*)d_in[1];
    const float* c0f  = (const float*)d_in[2];
    const float* h0b  = (const float*)d_in[3];
    const float* c0b  = (const float*)d_in[4];
    const float* Wxf  = (const float*)d_in[5];
    const float* Whf  = (const float*)d_in[6];
    const float* Wnf  = (const float*)d_in[7];
    const float* bf   = (const float*)d_in[8];
    const float* Wxb  = (const float*)d_in[9];
    const float* Whb  = (const float*)d_in[10];
    const float* Wnb  = (const float*)d_in[11];
    const float* bb   = (const float*)d_in[12];
    const float* Wff  = (const float*)d_in[13];
    const float* bff  = (const float*)d_in[14];
    const float* Wout = (const float*)d_in[15];
    const float* bout = (const float*)d_in[16];

    rec_kernel<TSTEPS><<<32768 / 32, 32>>>(x, h0f, c0f, h0b, c0b,
                                           Wxf, Whf, Wnf, bf,
                                           Wxb, Whb, Wnb, bb);
    ff_kernel<<<BSZ / 16, 128>>>(Wff, bff, Wout, bout, (float*)d_out);
}

// round 17
// speedup vs baseline: 1.8642x; 1.8642x over previous
#include <cuda_runtime.h>

#define BSZ 8192
#define TSTEPS 128
#define NN 25
// HID = 4, gates = 16

// Scratch (allocation-free rule: static __device__ arrays)
__device__ float g_xT[TSTEPS * NN * BSZ];       // [t][i][b]  ~105 MB
__device__ float g_H[BSZ * 200];                // final hidden concat, (bs, 200)

typedef unsigned long long u64;

// ---------------------------------------------------------------------------
// f32x2 packed helpers
// ---------------------------------------------------------------------------
__device__ __forceinline__ u64 packf2(float lo, float hi) {
    u64 r; asm("mov.b64 %0, {%1, %2};" : "=l"(r) : "f"(lo), "f"(hi)); return r;
}
__device__ __forceinline__ u64 bcast2(float v) { return packf2(v, v); }
__device__ __forceinline__ void unpackf2(u64 v, float& lo, float& hi) {
    asm("mov.b64 {%0, %1}, %2;" : "=f"(lo), "=f"(hi) : "l"(v));
}
__device__ __forceinline__ u64 fma2(u64 a, u64 b, u64 c) {
    u64 r; asm("fma.rn.f32x2 %0, %1, %2, %3;" : "=l"(r) : "l"(a), "l"(b), "l"(c));
    return r;
}
// 64-bit shuffles within the 4-lane group (2x SHFL.32)
__device__ __forceinline__ u64 shflx64(u64 v, int m) {
    unsigned lo = (unsigned)v, hi = (unsigned)(v >> 32);
    lo = __shfl_xor_sync(0xffffffffu, lo, m, 4);
    hi = __shfl_xor_sync(0xffffffffu, hi, m, 4);
    return ((u64)hi << 32) | lo;
}
__device__ __forceinline__ u64 shflb64(u64 v) {   // broadcast from lane 3 of group
    unsigned lo = (unsigned)v, hi = (unsigned)(v >> 32);
    lo = __shfl_sync(0xffffffffu, lo, 3, 4);
    hi = __shfl_sync(0xffffffffu, hi, 3, 4);
    return ((u64)hi << 32) | lo;
}

// ---------------------------------------------------------------------------
// cp.async helpers (8-byte LDGSTS)
// ---------------------------------------------------------------------------
__device__ __forceinline__ unsigned smem_u32(const void* p) {
    unsigned a;
    asm("{ .reg .u64 t; cvta.to.shared.u64 t, %1; cvt.u32.u64 %0, t; }"
        : "=r"(a) : "l"(p));
    return a;
}
__device__ __forceinline__ void cp_async8(unsigned dst, const void* src) {
    asm volatile("cp.async.ca.shared.global [%0], [%1], 8;" :: "r"(dst), "l"(src));
}
__device__ __forceinline__ void cp_commit() {
    asm volatile("cp.async.commit_group;");
}
template <int N>
__device__ __forceinline__ void cp_wait() {
    asm volatile("cp.async.wait_group %0;" :: "n"(N));
}

// ---------------------------------------------------------------------------
// MUFU.TANH-based activations (1 MUFU each) + precise sigmoid (FF head)
// ---------------------------------------------------------------------------
__device__ __forceinline__ float tanh_mufu(float x) {
    float y; asm("tanh.approx.f32 %0, %1;" : "=f"(y) : "f"(x)); return y;
}
__device__ __forceinline__ float sigf(float x) {   // precise (FF head)
    return __fdividef(1.0f, 1.0f + __expf(-x));
}

// ---------------------------------------------------------------------------
// Kernel 1: transpose x (bs, N, T) -> xT[t][i][b]
// ---------------------------------------------------------------------------
__global__ void transpose_kernel(const float* __restrict__ x) {
    __shared__ float tile[32][33];
    int i  = blockIdx.z;
    int b0 = blockIdx.x * 32;
    int t0 = blockIdx.y * 32;
    int tx = threadIdx.x, ty = threadIdx.y;
#pragma unroll
    for (int r = 0; r < 4; r++) {
        int b = b0 + ty + r * 8;
        int t = t0 + tx;
        tile[ty + r * 8][tx] = x[(b * NN + i) * TSTEPS + t];
    }
    __syncthreads();
#pragma unroll
    for (int r = 0; r < 4; r++) {
        int t = t0 + ty + r * 8;
        int b = b0 + tx;
        g_xT[(t * NN + i) * BSZ + b] = tile[tx][ty + r * 8];
    }
}

// ---------------------------------------------------------------------------
// Kernel 2: grid-LSTM recurrence (R15 structure — best measured: batch-pair
// f32x2, cp.async double-buffered x staging from the TRANSPOSED layout
// (coalesced — R16 proved the direct layout chokes the LSU on 32x sector
// divergence), f32 MUFU.TANH, chain-aware neighbor ordering).
// ONE-WARP BLOCKS: 1024 blocks spread 7/6 warps per SM instead of 512
// two-warp blocks spreading 8/6 — the max-loaded SM (the tail) drops 12.5%.
// ---------------------------------------------------------------------------
template <int STEPS>
__global__ __launch_bounds__(32) void rec_kernel(
    const float* __restrict__ h0f, const float* __restrict__ c0f,
    const float* __restrict__ h0b, const float* __restrict__ c0b,
    const float* __restrict__ Wxf, const float* __restrict__ Whf,
    const float* __restrict__ Wnf, const float* __restrict__ bf,
    const float* __restrict__ Wxb, const float* __restrict__ Whb,
    const float* __restrict__ Wnb, const float* __restrict__ bbk) {
    __shared__ u64 sm_x[2][NN][32];            // double-buffered x stage

    int tx   = threadIdx.x;
    int tid  = blockIdx.x * 32 + tx;           // 0 .. 32767
    int u    = tid & 3;
    int gid  = tid >> 2;                       // 0 .. 8191
    int pair = gid & 4095;
    int dir  = gid >> 12;                      // 0 = fwd, 1 = bwd
    int b0   = pair * 2;

    const float* Wx = dir ? Wxb : Wxf;
    const float* Wh = dir ? Whb : Whf;
    const float* Wn = dir ? Wnb : Wnf;
    const float* bv = dir ? bbk : bf;
    const float* h0 = dir ? h0b : h0f;
    const float* c0 = dir ? c0b : c0f;

    // Per-gate scale: 0.5 for sigmoid gates (g=0,1,2), 1.0 for cc (g=3)
    u64 wx2[4], b2[4], wh2[4][4], wu2[4], wd2[4], wl2[4], wr2[4];
    int rl = dir ? 3 : 2;   // Wn row providing LEFT weight
    int rr = dir ? 2 : 3;
#pragma unroll
    for (int g = 0; g < 4; g++) {
        float s   = (g == 3) ? 1.0f : 0.5f;
        int   col = g * 4 + u;
        wx2[g] = bcast2(s * Wx[col]);
        b2[g]  = bcast2(s * bv[col]);
#pragma unroll
        for (int j = 0; j < 4; j++)
            wh2[j][g] = bcast2(s * Wh[(u ^ j) * 16 + col]);  // j-th butterfly arrival
        wu2[g] = bcast2(s * Wn[0 * 16 + col]);
        wd2[g] = bcast2(s * Wn[1 * 16 + col]);
        wl2[g] = bcast2(s * Wn[rl * 16 + col]);
        wr2[g] = bcast2(s * Wn[rr * 16 + col]);
    }

    u64 h[NN];
    float ca[NN], cb[NN];
#pragma unroll
    for (int i = 0; i < NN; i++) {
        int base = (i * BSZ + b0) * 4 + u;
        h[i]  = packf2(h0[base], h0[base + 4]);
        ca[i] = c0[base];
        cb[i] = c0[base + 4];
    }

    // Stage timestep 0
    {
        int tt0 = dir ? (TSTEPS - 1) : 0;
        const u64* xr = (const u64*)(g_xT + (tt0 * NN) * BSZ + b0);
#pragma unroll
        for (int i = 0; i < NN; i++)
            cp_async8(smem_u32(&sm_x[0][i][tx]), xr + i * (BSZ / 2));
        cp_commit();
    }

#pragma unroll 1
    for (int t = 0; t < STEPS; t++) {
        int cur = t & 1;
        // stage t+1 while computing t
        if (t + 1 < STEPS) {
            int ttn = dir ? (TSTEPS - 2 - t) : (t + 1);
            const u64* xr = (const u64*)(g_xT + (ttn * NN) * BSZ + b0);
#pragma unroll
            for (int i = 0; i < NN; i++)
                cp_async8(smem_u32(&sm_x[cur ^ 1][i][tx]), xr + i * (BSZ / 2));
            cp_commit();
            cp_wait<1>();   // current-step group complete; next may be in flight
        } else {
            cp_wait<0>();
        }

#pragma unroll
        for (int i = 0; i < NN; i++) {
            u64 vx = sm_x[cur][i][tx];
            u64 v0 = h[i];
            // Issue ALL broadcasts up front; the chain-critical LEFT value's
            // SHFL latency is covered by the gate FMAs below.
            u64 nL = 0, nU = 0, nD = 0, nR = 0;
            if (i >= 1) nL = shflb64(h[i - 1]);   // fresh (this step)
            if (i >= 5) nU = shflb64(h[i - 5]);   // fresh
            if (i < 20) nD = shflb64(h[i + 5]);   // stale (prev step)
            if (i < 24) nR = shflb64(h[i + 1]);   // stale
            u64 v1 = shflx64(v0, 1);
            u64 v2 = shflx64(v0, 2);
            u64 v3 = shflx64(v1, 2);

            u64 G[4];
#pragma unroll
            for (int g = 0; g < 4; g++) {
                G[g] = fma2(vx, wx2[g], b2[g]);
                G[g] = fma2(v0, wh2[0][g], G[g]);
                G[g] = fma2(v1, wh2[1][g], G[g]);
                G[g] = fma2(v2, wh2[2][g], G[g]);
                G[g] = fma2(v3, wh2[3][g], G[g]);
            }
            if (i < 20) {
#pragma unroll
                for (int g = 0; g < 4; g++) G[g] = fma2(nD, wd2[g], G[g]);
            }
            if (i < 24) {
#pragma unroll
                for (int g = 0; g < 4; g++) G[g] = fma2(nR, wr2[g], G[g]);
            }
            if (i >= 5) {
#pragma unroll
                for (int g = 0; g < 4; g++) G[g] = fma2(nU, wu2[g], G[g]);
            }
            if (i >= 1) {   // LEFT term last: shortest exposure on the chain
#pragma unroll
                for (int g = 0; g < 4; g++) G[g] = fma2(nL, wl2[g], G[g]);
            }

            float i_a, i_b, f_a, f_b, o_a, o_b, c_a, c_b;
            unpackf2(G[0], i_a, i_b);
            unpackf2(G[1], f_a, f_b);
            unpackf2(G[2], o_a, o_b);
            unpackf2(G[3], c_a, c_b);

            // batch 0 (gates pre-scaled by 0.5 for sigmoids)
            float sia = fmaf(0.5f, tanh_mufu(i_a), 0.5f);
            float sfa = fmaf(0.5f, tanh_mufu(f_a), 0.5f);
            float soa = fmaf(0.5f, tanh_mufu(o_a), 0.5f);
            float tca = tanh_mufu(c_a);
            float nca = fmaf(sfa, ca[i], sia * tca);
            ca[i] = nca;
            float nha = soa * tanh_mufu(nca);
            // batch 1
            float sib = fmaf(0.5f, tanh_mufu(i_b), 0.5f);
            float sfb = fmaf(0.5f, tanh_mufu(f_b), 0.5f);
            float sob = fmaf(0.5f, tanh_mufu(o_b), 0.5f);
            float tcb = tanh_mufu(c_b);
            float ncb = fmaf(sfb, cb[i], sib * tcb);
            cb[i] = ncb;
            float nhb = sob * tanh_mufu(ncb);

            h[i] = packf2(nha, nhb);
        }
    }

    // H[b, i*8 + dir*4 + u] = h[i]
#pragma unroll
    for (int i = 0; i < NN; i++) {
        float ha, hb;
        unpackf2(h[i], ha, hb);
        g_H[b0 * 200 + i * 8 + dir * 4 + u]       = ha;
        g_H[(b0 + 1) * 200 + i * 8 + dir * 4 + u] = hb;
    }
}

// ---------------------------------------------------------------------------
// Kernel 3: FF head. 16 batch rows per block, 128 threads (one per neuron).
// ff = sigmoid(H @ W_ff + b_ff); out = softmax(ff @ W_out + b_out)
// ---------------------------------------------------------------------------
__global__ void ff_kernel(const float* __restrict__ Wff, const float* __restrict__ bff,
                          const float* __restrict__ Wout, const float* __restrict__ bout,
                          float* __restrict__ out) {
    __shared__ float Hs[16 * 200];
    __shared__ float Fs[16 * 128];
    int k  = threadIdx.x;        // neuron 0..127
    int b0 = blockIdx.x * 16;

    for (int idx = k; idx < 16 * 200; idx += 128)
        Hs[idx] = g_H[b0 * 200 + idx];
    __syncthreads();

    float acc[16];
    float bk = bff[k];
#pragma unroll
    for (int m = 0; m < 16; m++) acc[m] = bk;
#pragma unroll 4
    for (int j = 0; j < 200; j++) {
        float w = Wff[j * 128 + k];
#pragma unroll
        for (int m = 0; m < 16; m++) acc[m] = fmaf(Hs[m * 200 + j], w, acc[m]);
    }
#pragma unroll
    for (int m = 0; m < 16; m++) Fs[m * 128 + k] = sigf(acc[m]);
    __syncthreads();

    if (k < 16) {
        float s0 = bout[0], s1 = bout[1];
#pragma unroll 4
        for (int j = 0; j < 128; j++) {
            float f = Fs[k * 128 + j];
            s0 = fmaf(f, Wout[j * 2 + 0], s0);
            s1 = fmaf(f, Wout[j * 2 + 1], s1);
        }
        // softmax over 2 logits == sigmoid of difference
        out[(b0 + k) * 2 + 0] = sigf(s0 - s1);
        out[(b0 + k) * 2 + 1] = sigf(s1 - s0);
    }
}

// ---------------------------------------------------------------------------
extern "C" void kernel_launch(void* const* d_in, const int* in_sizes, int n_in,
                              void* d_out, int out_size) {
    const float* x    = (const float*)d_in[0];
    const float* h0f  = (const float*)d_in[1];
    const float* c0f  = (const float*)d_in[2];
    const float* h0b  = (const float*)d_in[3];
    const float* c0b  = (const float*)d_in[4];
    const float* Wxf  = (const float*)d_in[5];
    const float* Whf  = (const float*)d_in[6];
    const float* Wnf  = (const float*)d_in[7];
    const float* bf   = (const float*)d_in[8];
    const float* Wxb  = (const float*)d_in[9];
    const float* Whb  = (const float*)d_in[10];
    const float* Wnb  = (const float*)d_in[11];
    const float* bb   = (const float*)d_in[12];
    const float* Wff  = (const float*)d_in[13];
    const float* bff  = (const float*)d_in[14];
    const float* Wout = (const float*)d_in[15];
    const float* bout = (const float*)d_in[16];

    transpose_kernel<<<dim3(BSZ / 32, TSTEPS / 32, NN), dim3(32, 8)>>>(x);
    rec_kernel<TSTEPS><<<32768 / 32, 32>>>(h0f, c0f, h0b, c0b,
                                           Wxf, Whf, Wnf, bf,
                                           Wxb, Whb, Wnb, bb);
    ff_kernel<<<BSZ / 16, 128>>>(Wff, bff, Wout, bout, (float*)d_out);
}